// round 13
// baseline (speedup 1.0000x reference)
#include <cuda_runtime.h>
#include <cuda_fp16.h>
#include <cstdint>

// Shapes (fixed by the problem)
#define B_ 2
#define S_ 1024
#define H_ 512
#define A_ 128

#define CTAS_PER_B 74            // 148 attn CTAs total, 13-14 rows each, 1 CTA/SM
#define MAXR 16
#define TJ 128
#define NT 8                     // S_/TJ tiles

// ---------------- scratch (no allocation allowed) ----------------
__device__ __half2 g_wxh [B_ * S_ * (A_ / 2)];    // [m][a2] packed a-pairs (0.5 MB)
__device__ __half2 g_uxth[B_ * (A_ / 2) * S_];    // [b][a2][s] packed a-pairs (0.5 MB)
__device__ float   g_colsum[B_ * S_];

__device__ __forceinline__ __half2 tanh2h(__half2 x) {
    uint32_t xi = *(uint32_t*)&x, yi;
    asm("tanh.approx.f16x2 %0, %1;" : "=r"(yi) : "r"(xi));
    return *(__half2*)&yi;
}

__device__ __forceinline__ void cp16(void* dst_smem, const void* src) {
    uint32_t d = (uint32_t)__cvta_generic_to_shared(dst_smem);
    asm volatile("cp.async.cg.shared.global [%0], [%1], 16;\n" :: "r"(d), "l"(src));
}
#define CP_COMMIT() asm volatile("cp.async.commit_group;\n")
#define CP_WAIT(N)  asm volatile("cp.async.wait_group %0;\n" :: "n"(N))

// ---------------- kernel 1: wxh = pack(lstm@w), uxth = pack(lstm@u)^T ----------------
// BM=32 x BN=64, 256 threads (2x4 microtile), grid (64, 4) = 256 CTAs, ~14 warps/SM
#define BK 16
__global__ __launch_bounds__(256) void gemm_wxux(
    const float* __restrict__ lstm, const float* __restrict__ w, const float* __restrict__ u,
    float* __restrict__ ctx)
{
    __shared__ float As[BK][32];
    __shared__ float Bs[BK][64];
    int tid = threadIdx.x;

    if (blockIdx.x == 0 && blockIdx.y == 0) {      // fused zeroing
        for (int t = tid; t < B_ * S_; t += 256) g_colsum[t] = 0.0f;
        for (int t = tid; t < B_ * H_; t += 256) ctx[t] = 0.0f;
    }

    int m0 = blockIdx.x * 32;                      // 64 blocks over m
    int n0 = blockIdx.y * 64;                      // 0,64 -> w ; 128,192 -> u
    const float* bsrc = (n0 < A_) ? (w + n0) : (u + (n0 - A_));

    int tm = (tid >> 4) * 2;                       // 0..30
    int tn = (tid & 15) * 4;                       // 0..60
    int la_m = tid >> 2;                           // 0..31 (tid<128 only)
    int la_k = (tid & 3) * 4;                      // 0,4,8,12
    int lb_k = tid >> 4;                           // 0..15
    int lb_n = (tid & 15) * 4;                     // 0..60

    const float* a_ptr = lstm + (size_t)(m0 + la_m) * H_ + la_k;
    const float* b_ptr = bsrc + (size_t)lb_k * A_ + lb_n;

    float acc[2][4];
#pragma unroll
    for (int i = 0; i < 2; i++)
#pragma unroll
        for (int j = 0; j < 4; j++) acc[i][j] = 0.0f;

    // pipeline prologue: load k-step 0
    float4 av = make_float4(0.f, 0.f, 0.f, 0.f);
    if (tid < 128) av = *(const float4*)(a_ptr);
    float4 bv = *(const float4*)(b_ptr);

    for (int k0 = 0; k0 < H_; k0 += BK) {
        __syncthreads();
        if (tid < 128) {
            As[la_k + 0][la_m] = av.x;
            As[la_k + 1][la_m] = av.y;
            As[la_k + 2][la_m] = av.z;
            As[la_k + 3][la_m] = av.w;
        }
        *(float4*)&Bs[lb_k][lb_n] = bv;
        __syncthreads();

        if (k0 + BK < H_) {                        // prefetch next k-step before compute
            if (tid < 128) av = *(const float4*)(a_ptr + (k0 + BK));
            bv = *(const float4*)(b_ptr + (size_t)(k0 + BK) * A_);
        }

#pragma unroll
        for (int kk = 0; kk < BK; kk++) {
            float2 a2 = *(const float2*)&As[kk][tm];
            float4 b4 = *(const float4*)&Bs[kk][tn];
            acc[0][0] = fmaf(a2.x, b4.x, acc[0][0]);
            acc[0][1] = fmaf(a2.x, b4.y, acc[0][1]);
            acc[0][2] = fmaf(a2.x, b4.z, acc[0][2]);
            acc[0][3] = fmaf(a2.x, b4.w, acc[0][3]);
            acc[1][0] = fmaf(a2.y, b4.x, acc[1][0]);
            acc[1][1] = fmaf(a2.y, b4.y, acc[1][1]);
            acc[1][2] = fmaf(a2.y, b4.z, acc[1][2]);
            acc[1][3] = fmaf(a2.y, b4.w, acc[1][3]);
        }
    }

    if (n0 < A_) {
        // wx: pack a-pairs -> g_wxh[m][a2]
#pragma unroll
        for (int i = 0; i < 2; i++) {
            int m = m0 + tm + i;
            __half2 p0 = __floats2half2_rn(acc[i][0], acc[i][1]);
            __half2 p1 = __floats2half2_rn(acc[i][2], acc[i][3]);
            __half2* dst = g_wxh + (size_t)m * (A_ / 2) + (n0 + tn) / 2;
            dst[0] = p0;
            dst[1] = p1;
        }
    } else {
        // ux: pack a-pairs, transposed -> g_uxth[b][a2][s]
        int b  = m0 >> 10;
        int s0 = (m0 & (S_ - 1)) + tm;
        int a0 = (n0 - A_) + tn;                   // multiple of 4
        __half2* base = g_uxth + (size_t)b * (A_ / 2) * S_;
#pragma unroll
        for (int i = 0; i < 2; i++) {
            base[(size_t)(a0 / 2 + 0) * S_ + s0 + i] = __floats2half2_rn(acc[i][0], acc[i][1]);
            base[(size_t)(a0 / 2 + 1) * S_ + s0 + i] = __floats2half2_rn(acc[i][2], acc[i][3]);
        }
    }
}

// ---------------- kernel 2: f16-native e kernel (R12, unchanged) ----------------
// dyn smem: wx_h[16][64] half2 (4KB) + uxh 2x[64][TJ] half2 (2x32KB) + v_h[64] ~68.5KB
__global__ __launch_bounds__(512) void attn_e_kernel(
    const float* __restrict__ v, float* __restrict__ attn_out)
{
    extern __shared__ float sm[];
    __half2* wx_h = (__half2*)sm;                  // MAXR*64
    __half2* uxh0 = wx_h + MAXR * (A_ / 2);        // 64 rows x TJ half2
    __half2* uxh1 = uxh0 + 64 * TJ;                // 64 rows x TJ half2
    __half2* v_h  = uxh1 + 64 * TJ;                // 64

    int tid  = threadIdx.x;
    int warp = tid >> 5;
    int lane = tid & 31;
    int blk  = blockIdx.x;                         // 148 blocks
    int b    = blk / CTAS_PER_B;
    int t_   = blk % CTAS_PER_B;
    int i0   = (S_ * t_) / CTAS_PER_B;
    int i1   = (S_ * (t_ + 1)) / CTAS_PER_B;
    int nr   = i1 - i0;                            // 13 or 14

    const __half2* uxt_b = g_uxth + (size_t)b * (A_ / 2) * S_;
    int pr = tid >> 3;                             // a2 row 0..63
    int pc = tid & 7;                              // base chunk 0..7

    // prefetch tile 0: 64 rows x 128 half2 = 32KB -> 2048 cp16 (4 per thread)
#pragma unroll
    for (int k = 0; k < 4; k++) {
        int c = 4 * (pc + 8 * k);                  // half2 offset 0..124
        cp16(uxh0 + pr * TJ + c, uxt_b + (size_t)pr * S_ + c);
    }
    CP_COMMIT();

    // stage wx rows (nr x 64 half2 = nr*256B) as uint4
    for (int x = tid; x < nr * 16; x += 512) {
        int r = x >> 4, c = x & 15;
        ((uint4*)(wx_h + r * (A_ / 2)))[c] =
            ((const uint4*)(g_wxh + (size_t)(b * S_ + i0 + r) * (A_ / 2)))[c];
    }
    if (tid < 64) v_h[tid] = __floats2half2_rn(v[2 * tid], v[2 * tid + 1]);

    bool active = (warp < nr);
    float er[4 * NT];

#pragma unroll
    for (int t = 0; t < NT; t++) {
        __half2* cur = (t & 1) ? uxh1 : uxh0;
        if (t + 1 < NT) {
            __half2* nxt = ((t + 1) & 1) ? uxh1 : uxh0;
            const __half2* src = uxt_b + (size_t)(t + 1) * TJ;
#pragma unroll
            for (int k = 0; k < 4; k++) {
                int c = 4 * (pc + 8 * k);
                cp16(nxt + pr * TJ + c, src + (size_t)pr * S_ + c);
            }
            CP_COMMIT();
            CP_WAIT(1);
        } else {
            CP_WAIT(0);
        }
        __syncthreads();

        if (active) {
            float accf0 = 0.f, accf1 = 0.f, accf2 = 0.f, accf3 = 0.f;
            const __half2* wrow = wx_h + warp * (A_ / 2);
            const __half2* ub   = cur + 4 * lane;  // this thread's 4 j-slots

#pragma unroll
            for (int g = 0; g < 8; g++) {          // spill to f32 every 16 a's
                __half2 h0 = __float2half2_rn(0.f);
                __half2 h1 = __float2half2_rn(0.f);
                __half2 h2 = __float2half2_rn(0.f);
                __half2 h3 = __float2half2_rn(0.f);
#pragma unroll
                for (int q = 0; q < 4; q++) {      // a4 = 4g+q : 4 a's = 2 tile rows
                    int a4 = 4 * g + q;
                    __half2 wh0 = wrow[2 * a4 + 0];
                    __half2 wh1 = wrow[2 * a4 + 1];
                    __half2 vh0 = v_h[2 * a4 + 0];
                    __half2 vh1 = v_h[2 * a4 + 1];
                    const __half2* r0 = ub + (size_t)(2 * a4 + 0) * TJ;
                    const __half2* r1 = ub + (size_t)(2 * a4 + 1) * TJ;
                    __half2 u00 = r0[0], u01 = r0[1], u02 = r0[2], u03 = r0[3];
                    __half2 u10 = r1[0], u11 = r1[1], u12 = r1[2], u13 = r1[3];
                    h0 = __hfma2(tanh2h(__hadd2(wh0, u00)), vh0, h0);
                    h1 = __hfma2(tanh2h(__hadd2(wh0, u01)), vh0, h1);
                    h2 = __hfma2(tanh2h(__hadd2(wh0, u02)), vh0, h2);
                    h3 = __hfma2(tanh2h(__hadd2(wh0, u03)), vh0, h3);
                    h0 = __hfma2(tanh2h(__hadd2(wh1, u10)), vh1, h0);
                    h1 = __hfma2(tanh2h(__hadd2(wh1, u11)), vh1, h1);
                    h2 = __hfma2(tanh2h(__hadd2(wh1, u12)), vh1, h2);
                    h3 = __hfma2(tanh2h(__hadd2(wh1, u13)), vh1, h3);
                }
                float2 f0 = __half22float2(h0);
                float2 f1 = __half22float2(h1);
                float2 f2 = __half22float2(h2);
                float2 f3 = __half22float2(h3);
                accf0 += f0.x + f0.y;
                accf1 += f1.x + f1.y;
                accf2 += f2.x + f2.y;
                accf3 += f3.x + f3.y;
            }
            er[4 * t + 0] = accf0;
            er[4 * t + 1] = accf1;
            er[4 * t + 2] = accf2;
            er[4 * t + 3] = accf3;
        }
        __syncthreads();
    }

    // slots region: uxh0+uxh1 = 64KB contiguous, need nr*1024*4 <= 56KB
    float* slots = (float*)uxh0;
    if (active) {
        float m = er[0];
#pragma unroll
        for (int k = 1; k < 4 * NT; k++) m = fmaxf(m, er[k]);
#pragma unroll
        for (int o = 16; o; o >>= 1) m = fmaxf(m, __shfl_xor_sync(0xffffffffu, m, o));
        float s = 0.f;
#pragma unroll
        for (int k = 0; k < 4 * NT; k++) {
            er[k] = __expf(er[k] - m);
            s += er[k];
        }
#pragma unroll
        for (int o = 16; o; o >>= 1) s += __shfl_xor_sync(0xffffffffu, s, o);
        float inv = 1.0f / s;
        float* orow = attn_out + (size_t)(b * S_ + i0 + warp) * S_;
        float* srow = slots + (size_t)warp * S_;
#pragma unroll
        for (int ti = 0; ti < NT; ti++) {
            float4 o = make_float4(er[4 * ti] * inv, er[4 * ti + 1] * inv,
                                   er[4 * ti + 2] * inv, er[4 * ti + 3] * inv);
            *(float4*)(orow + ti * TJ + 4 * lane) = o;
            *(float4*)(srow + ti * TJ + 4 * lane) = o;
        }
    }
    __syncthreads();

    for (int j = tid; j < S_; j += 512) {
        float s = 0.f;
        for (int r = 0; r < nr; r++) s += slots[(size_t)r * S_ + j];
        atomicAdd(&g_colsum[b * S_ + j], s);
    }
}

// ---------------- kernel 3: context[b,h] = sum_j colsum[b,j] * lstm[b,j,h] ----------------
__global__ __launch_bounds__(512) void context_kernel(
    const float* __restrict__ lstm, float* __restrict__ ctx)
{
    int b  = blockIdx.x >> 6;                      // 2 * 64 blocks
    int j0 = (blockIdx.x & 63) * 16;
    int h  = threadIdx.x;
    __shared__ float cs[16];
    if (threadIdx.x < 16) cs[threadIdx.x] = g_colsum[b * S_ + j0 + threadIdx.x];
    __syncthreads();
    float acc = 0.f;
    const float* lp = lstm + ((size_t)(b * S_ + j0)) * H_ + h;
#pragma unroll
    for (int j = 0; j < 16; j++) acc = fmaf(cs[j], lp[(size_t)j * H_], acc);
    atomicAdd(&ctx[b * H_ + h], acc);
}

// ---------------- launch (single stream, deterministic) ----------------
extern "C" void kernel_launch(void* const* d_in, const int* in_sizes, int n_in,
                              void* d_out, int out_size)
{
    const float* lstm = (const float*)d_in[0];
    const float* w    = (const float*)d_in[1];
    const float* u    = (const float*)d_in[2];
    const float* v    = (const float*)d_in[3];
    float* out  = (float*)d_out;
    float* ctx  = out;                // (B,H) = 1024 floats first
    float* attn = out + B_ * H_;      // (B,S,S) = 2M floats after

    gemm_wxux<<<dim3(64, 4), 256>>>(lstm, w, u, ctx);

    size_t smem = (size_t)(MAXR * (A_ / 2) + 2 * 64 * TJ + 64) * sizeof(__half2); // ~68.5 KB
    cudaFuncSetAttribute(attn_e_kernel, cudaFuncAttributeMaxDynamicSharedMemorySize, (int)smem);
    attn_e_kernel<<<B_ * CTAS_PER_B, 512, smem>>>(v, attn);

    context_kernel<<<B_ * 64, 512>>>(lstm, ctx);
}

// round 14
// speedup vs baseline: 1.1153x; 1.1153x over previous
#include <cuda_runtime.h>
#include <cuda_fp16.h>
#include <cstdint>

// Shapes (fixed by the problem)
#define B_ 2
#define S_ 1024
#define H_ 512
#define A_ 128

#define CTAS_PER_B 74            // 148 attn CTAs total, 13-14 rows each, 1 CTA/SM
#define MAXR 16
#define TJ 128
#define NT 8                     // S_/TJ tiles

// ---------------- scratch (no allocation allowed) ----------------
__device__ __half2 g_wxh [B_ * S_ * (A_ / 2)];    // [m][a2] packed a-pairs (0.5 MB)
__device__ __half2 g_uxth[B_ * (A_ / 2) * S_];    // [b][a2][s] packed a-pairs (0.5 MB)
__device__ float   g_colsum[B_ * S_];

__device__ __forceinline__ __half2 tanh2h(__half2 x) {
    uint32_t xi = *(uint32_t*)&x, yi;
    asm("tanh.approx.f16x2 %0, %1;" : "=r"(yi) : "r"(xi));
    return *(__half2*)&yi;
}

__device__ __forceinline__ void cp16(void* dst_smem, const void* src) {
    uint32_t d = (uint32_t)__cvta_generic_to_shared(dst_smem);
    asm volatile("cp.async.cg.shared.global [%0], [%1], 16;\n" :: "r"(d), "l"(src));
}
#define CP_COMMIT() asm volatile("cp.async.commit_group;\n")
#define CP_WAIT(N)  asm volatile("cp.async.wait_group %0;\n" :: "n"(N))

// ---------------- kernel 1: wxh = pack(lstm@w), uxth = pack(lstm@u)^T ----------------
// BM=32 x BN=64, 128 threads, 4x4 microtile, grid (64,4)=256 CTAs.
// Double-buffered smem: cp.async for B, register-prefetch for A, ONE sync per BK step.
#define BK 16
__global__ __launch_bounds__(128) void gemm_wxux(
    const float* __restrict__ lstm, const float* __restrict__ w, const float* __restrict__ u,
    float* __restrict__ ctx)
{
    __shared__ float As[2][BK][32];
    __shared__ float Bs[2][BK][64];
    int tid = threadIdx.x;

    if (blockIdx.x == 0 && blockIdx.y == 0) {      // fused zeroing
        for (int t = tid; t < B_ * S_; t += 128) g_colsum[t] = 0.0f;
        for (int t = tid; t < B_ * H_; t += 128) ctx[t] = 0.0f;
    }

    int m0 = blockIdx.x * 32;                      // 64 blocks over m
    int n0 = blockIdx.y * 64;                      // 0,64 -> w ; 128,192 -> u
    const float* bsrc = (n0 < A_) ? (w + n0) : (u + (n0 - A_));

    int tm = (tid >> 4) * 4;                       // 0..28
    int tn = (tid & 15) * 4;                       // 0..60
    int la_m = tid >> 2;                           // 0..31
    int la_k = (tid & 3) * 4;                      // 0,4,8,12

    // B cp.async mapping: 2 chunks of 16B per thread covering 16x64 tile
    int b0_row = tid >> 4;                         // chunk 0: rows 0..7  (idx = tid)
    int b0_col = (tid & 15) * 4;
    int b1_row = (tid + 128) >> 4;                 // chunk 1: rows 8..15
    int b1_col = b0_col;

    const float* a_ptr = lstm + (size_t)(m0 + la_m) * H_ + la_k;

    float acc[4][4];
#pragma unroll
    for (int i = 0; i < 4; i++)
#pragma unroll
        for (int j = 0; j < 4; j++) acc[i][j] = 0.0f;

    // prologue: A k-step 0 into regs, B k-step 0 via cp.async into stage 0
    float4 av = *(const float4*)(a_ptr);
    cp16(&Bs[0][b0_row][b0_col], bsrc + (size_t)b0_row * A_ + b0_col);
    cp16(&Bs[0][b1_row][b1_col], bsrc + (size_t)b1_row * A_ + b1_col);
    CP_COMMIT();

    int s = 0;
    for (int k0 = 0; k0 < H_; k0 += BK, s ^= 1) {
        // stash current A into As[s]
        As[s][la_k + 0][la_m] = av.x;
        As[s][la_k + 1][la_m] = av.y;
        As[s][la_k + 2][la_m] = av.z;
        As[s][la_k + 3][la_m] = av.w;

        CP_WAIT(0);                                // current-stage B landed
        __syncthreads();                           // A visible; prev compute done

        if (k0 + BK < H_) {                        // prefetch next stage
            av = *(const float4*)(a_ptr + (k0 + BK));
            const float* bn_ = bsrc + (size_t)(k0 + BK) * A_;
            cp16(&Bs[s ^ 1][b0_row][b0_col], bn_ + (size_t)b0_row * A_ + b0_col);
            cp16(&Bs[s ^ 1][b1_row][b1_col], bn_ + (size_t)b1_row * A_ + b1_col);
            CP_COMMIT();
        }

#pragma unroll
        for (int kk = 0; kk < BK; kk++) {
            float4 a4 = *(const float4*)&As[s][kk][tm];
            float4 b4 = *(const float4*)&Bs[s][kk][tn];
            float am[4] = {a4.x, a4.y, a4.z, a4.w};
            float bn[4] = {b4.x, b4.y, b4.z, b4.w};
#pragma unroll
            for (int i = 0; i < 4; i++)
#pragma unroll
                for (int j = 0; j < 4; j++) acc[i][j] = fmaf(am[i], bn[j], acc[i][j]);
        }
    }

    if (n0 < A_) {
        // wx: pack a-pairs -> g_wxh[m][a2]
#pragma unroll
        for (int i = 0; i < 4; i++) {
            int m = m0 + tm + i;
            __half2 p0 = __floats2half2_rn(acc[i][0], acc[i][1]);
            __half2 p1 = __floats2half2_rn(acc[i][2], acc[i][3]);
            __half2* dst = g_wxh + (size_t)m * (A_ / 2) + (n0 + tn) / 2;
            dst[0] = p0;
            dst[1] = p1;
        }
    } else {
        // ux: pack a-pairs, transposed -> g_uxth[b][a2][s]
        int b  = m0 >> 10;
        int s0 = (m0 & (S_ - 1)) + tm;
        int a0 = (n0 - A_) + tn;                   // multiple of 4
        __half2* base = g_uxth + (size_t)b * (A_ / 2) * S_;
#pragma unroll
        for (int i = 0; i < 4; i++) {
            base[(size_t)(a0 / 2 + 0) * S_ + s0 + i] = __floats2half2_rn(acc[i][0], acc[i][1]);
            base[(size_t)(a0 / 2 + 1) * S_ + s0 + i] = __floats2half2_rn(acc[i][2], acc[i][3]);
        }
    }
}

// ---------------- kernel 2: f16-native e kernel (R12, unchanged) ----------------
// dyn smem: wx_h[16][64] half2 (4KB) + uxh 2x[64][TJ] half2 (2x32KB) + v_h[64] ~68.5KB
__global__ __launch_bounds__(512) void attn_e_kernel(
    const float* __restrict__ v, float* __restrict__ attn_out)
{
    extern __shared__ float sm[];
    __half2* wx_h = (__half2*)sm;                  // MAXR*64
    __half2* uxh0 = wx_h + MAXR * (A_ / 2);        // 64 rows x TJ half2
    __half2* uxh1 = uxh0 + 64 * TJ;                // 64 rows x TJ half2
    __half2* v_h  = uxh1 + 64 * TJ;                // 64

    int tid  = threadIdx.x;
    int warp = tid >> 5;
    int lane = tid & 31;
    int blk  = blockIdx.x;                         // 148 blocks
    int b    = blk / CTAS_PER_B;
    int t_   = blk % CTAS_PER_B;
    int i0   = (S_ * t_) / CTAS_PER_B;
    int i1   = (S_ * (t_ + 1)) / CTAS_PER_B;
    int nr   = i1 - i0;                            // 13 or 14

    const __half2* uxt_b = g_uxth + (size_t)b * (A_ / 2) * S_;
    int pr = tid >> 3;                             // a2 row 0..63
    int pc = tid & 7;                              // base chunk 0..7

    // prefetch tile 0: 64 rows x 128 half2 = 32KB -> 2048 cp16 (4 per thread)
#pragma unroll
    for (int k = 0; k < 4; k++) {
        int c = 4 * (pc + 8 * k);                  // half2 offset 0..124
        cp16(uxh0 + pr * TJ + c, uxt_b + (size_t)pr * S_ + c);
    }
    CP_COMMIT();

    // stage wx rows (nr x 64 half2 = nr*256B) as uint4
    for (int x = tid; x < nr * 16; x += 512) {
        int r = x >> 4, c = x & 15;
        ((uint4*)(wx_h + r * (A_ / 2)))[c] =
            ((const uint4*)(g_wxh + (size_t)(b * S_ + i0 + r) * (A_ / 2)))[c];
    }
    if (tid < 64) v_h[tid] = __floats2half2_rn(v[2 * tid], v[2 * tid + 1]);

    bool active = (warp < nr);
    float er[4 * NT];

#pragma unroll
    for (int t = 0; t < NT; t++) {
        __half2* cur = (t & 1) ? uxh1 : uxh0;
        if (t + 1 < NT) {
            __half2* nxt = ((t + 1) & 1) ? uxh1 : uxh0;
            const __half2* src = uxt_b + (size_t)(t + 1) * TJ;
#pragma unroll
            for (int k = 0; k < 4; k++) {
                int c = 4 * (pc + 8 * k);
                cp16(nxt + pr * TJ + c, src + (size_t)pr * S_ + c);
            }
            CP_COMMIT();
            CP_WAIT(1);
        } else {
            CP_WAIT(0);
        }
        __syncthreads();

        if (active) {
            float accf0 = 0.f, accf1 = 0.f, accf2 = 0.f, accf3 = 0.f;
            const __half2* wrow = wx_h + warp * (A_ / 2);
            const __half2* ub   = cur + 4 * lane;  // this thread's 4 j-slots

#pragma unroll
            for (int g = 0; g < 8; g++) {          // spill to f32 every 16 a's
                __half2 h0 = __float2half2_rn(0.f);
                __half2 h1 = __float2half2_rn(0.f);
                __half2 h2 = __float2half2_rn(0.f);
                __half2 h3 = __float2half2_rn(0.f);
#pragma unroll
                for (int q = 0; q < 4; q++) {      // a4 = 4g+q : 4 a's = 2 tile rows
                    int a4 = 4 * g + q;
                    __half2 wh0 = wrow[2 * a4 + 0];
                    __half2 wh1 = wrow[2 * a4 + 1];
                    __half2 vh0 = v_h[2 * a4 + 0];
                    __half2 vh1 = v_h[2 * a4 + 1];
                    const __half2* r0 = ub + (size_t)(2 * a4 + 0) * TJ;
                    const __half2* r1 = ub + (size_t)(2 * a4 + 1) * TJ;
                    __half2 u00 = r0[0], u01 = r0[1], u02 = r0[2], u03 = r0[3];
                    __half2 u10 = r1[0], u11 = r1[1], u12 = r1[2], u13 = r1[3];
                    h0 = __hfma2(tanh2h(__hadd2(wh0, u00)), vh0, h0);
                    h1 = __hfma2(tanh2h(__hadd2(wh0, u01)), vh0, h1);
                    h2 = __hfma2(tanh2h(__hadd2(wh0, u02)), vh0, h2);
                    h3 = __hfma2(tanh2h(__hadd2(wh0, u03)), vh0, h3);
                    h0 = __hfma2(tanh2h(__hadd2(wh1, u10)), vh1, h0);
                    h1 = __hfma2(tanh2h(__hadd2(wh1, u11)), vh1, h1);
                    h2 = __hfma2(tanh2h(__hadd2(wh1, u12)), vh1, h2);
                    h3 = __hfma2(tanh2h(__hadd2(wh1, u13)), vh1, h3);
                }
                float2 f0 = __half22float2(h0);
                float2 f1 = __half22float2(h1);
                float2 f2 = __half22float2(h2);
                float2 f3 = __half22float2(h3);
                accf0 += f0.x + f0.y;
                accf1 += f1.x + f1.y;
                accf2 += f2.x + f2.y;
                accf3 += f3.x + f3.y;
            }
            er[4 * t + 0] = accf0;
            er[4 * t + 1] = accf1;
            er[4 * t + 2] = accf2;
            er[4 * t + 3] = accf3;
        }
        __syncthreads();
    }

    // slots region: uxh0+uxh1 = 64KB contiguous, need nr*1024*4 <= 56KB
    float* slots = (float*)uxh0;
    if (active) {
        float m = er[0];
#pragma unroll
        for (int k = 1; k < 4 * NT; k++) m = fmaxf(m, er[k]);
#pragma unroll
        for (int o = 16; o; o >>= 1) m = fmaxf(m, __shfl_xor_sync(0xffffffffu, m, o));
        float s = 0.f;
#pragma unroll
        for (int k = 0; k < 4 * NT; k++) {
            er[k] = __expf(er[k] - m);
            s += er[k];
        }
#pragma unroll
        for (int o = 16; o; o >>= 1) s += __shfl_xor_sync(0xffffffffu, s, o);
        float inv = 1.0f / s;
        float* orow = attn_out + (size_t)(b * S_ + i0 + warp) * S_;
        float* srow = slots + (size_t)warp * S_;
#pragma unroll
        for (int ti = 0; ti < NT; ti++) {
            float4 o = make_float4(er[4 * ti] * inv, er[4 * ti + 1] * inv,
                                   er[4 * ti + 2] * inv, er[4 * ti + 3] * inv);
            *(float4*)(orow + ti * TJ + 4 * lane) = o;
            *(float4*)(srow + ti * TJ + 4 * lane) = o;
        }
    }
    __syncthreads();

    for (int j = tid; j < S_; j += 512) {
        float s = 0.f;
        for (int r = 0; r < nr; r++) s += slots[(size_t)r * S_ + j];
        atomicAdd(&g_colsum[b * S_ + j], s);
    }
}

// ---------------- kernel 3: context[b,h] = sum_j colsum[b,j] * lstm[b,j,h] ----------------
__global__ __launch_bounds__(512) void context_kernel(
    const float* __restrict__ lstm, float* __restrict__ ctx)
{
    int b  = blockIdx.x >> 6;                      // 2 * 64 blocks
    int j0 = (blockIdx.x & 63) * 16;
    int h  = threadIdx.x;
    __shared__ float cs[16];
    if (threadIdx.x < 16) cs[threadIdx.x] = g_colsum[b * S_ + j0 + threadIdx.x];
    __syncthreads();
    float acc = 0.f;
    const float* lp = lstm + ((size_t)(b * S_ + j0)) * H_ + h;
#pragma unroll
    for (int j = 0; j < 16; j++) acc = fmaf(cs[j], lp[(size_t)j * H_], acc);
    atomicAdd(&ctx[b * H_ + h], acc);
}

// ---------------- launch (single stream, deterministic) ----------------
extern "C" void kernel_launch(void* const* d_in, const int* in_sizes, int n_in,
                              void* d_out, int out_size)
{
    const float* lstm = (const float*)d_in[0];
    const float* w    = (const float*)d_in[1];
    const float* u    = (const float*)d_in[2];
    const float* v    = (const float*)d_in[3];
    float* out  = (float*)d_out;
    float* ctx  = out;                // (B,H) = 1024 floats first
    float* attn = out + B_ * H_;      // (B,S,S) = 2M floats after

    gemm_wxux<<<dim3(64, 4), 128>>>(lstm, w, u, ctx);

    size_t smem = (size_t)(MAXR * (A_ / 2) + 2 * 64 * TJ + 64) * sizeof(__half2); // ~68.5 KB
    cudaFuncSetAttribute(attn_e_kernel, cudaFuncAttributeMaxDynamicSharedMemorySize, (int)smem);
    attn_e_kernel<<<B_ * CTAS_PER_B, 512, smem>>>(v, attn);

    context_kernel<<<B_ * 64, 512>>>(lstm, ctx);
}

// round 16
// speedup vs baseline: 1.1333x; 1.0162x over previous
#include <cuda_runtime.h>
#include <cuda_fp16.h>
#include <cstdint>

// Shapes (fixed by the problem)
#define B_ 2
#define S_ 1024
#define H_ 512
#define A_ 128

#define CTAS_PER_B 74            // 148 attn CTAs total, 13-14 rows each, 1 CTA/SM
#define MAXR 16
#define TJ 128
#define NT 8                     // S_/TJ tiles

// ---------------- scratch (no allocation allowed) ----------------
__device__ __half2 g_wxh [B_ * S_ * (A_ / 2)];    // [m][a2] packed a-pairs (0.5 MB)
__device__ __half2 g_uxth[B_ * (A_ / 2) * S_];    // [b][a2][s] packed a-pairs (0.5 MB)
__device__ float   g_colsum[B_ * S_];

__device__ __forceinline__ __half2 tanh2h(__half2 x) {
    uint32_t xi = *(uint32_t*)&x, yi;
    asm("tanh.approx.f16x2 %0, %1;" : "=r"(yi) : "r"(xi));
    return *(__half2*)&yi;
}

__device__ __forceinline__ void cp16(void* dst_smem, const void* src) {
    uint32_t d = (uint32_t)__cvta_generic_to_shared(dst_smem);
    asm volatile("cp.async.cg.shared.global [%0], [%1], 16;\n" :: "r"(d), "l"(src));
}
#define CP_COMMIT() asm volatile("cp.async.commit_group;\n")
#define CP_WAIT(N)  asm volatile("cp.async.wait_group %0;\n" :: "n"(N))

// ---------------- kernel 1: wxh = pack(lstm@w), uxth = pack(lstm@u)^T ----------------
// BM=32 x BN=64, 256 threads as TWO 128-thread k-split groups (k 0-255 / 256-511).
// Each group: 4x4 microtile, double-buffered cp.async B + register-prefetch A.
// Cross-group f32 reduction in smem at the end. grid (64,4)=256 CTAs, 14 warps/SM.
#define BK 16
#define KSPLIT 256
__global__ __launch_bounds__(256) void gemm_wxux(
    const float* __restrict__ lstm, const float* __restrict__ w, const float* __restrict__ u,
    float* __restrict__ ctx)
{
    __shared__ float As[2][2][BK][32];             // [group][stage]
    __shared__ float Bs[2][2][BK][64];
    __shared__ float red[128 * 17];                // padded, conflict-free
    int tid  = threadIdx.x;
    int g    = tid >> 7;                           // k-split group 0/1
    int ltid = tid & 127;

    if (blockIdx.x == 0 && blockIdx.y == 0) {      // fused zeroing
        for (int t = tid; t < B_ * S_; t += 256) g_colsum[t] = 0.0f;
        for (int t = tid; t < B_ * H_; t += 256) ctx[t] = 0.0f;
    }

    int m0 = blockIdx.x * 32;                      // 64 blocks over m
    int n0 = blockIdx.y * 64;                      // 0,64 -> w ; 128,192 -> u
    const float* bsrc = (n0 < A_) ? (w + n0) : (u + (n0 - A_));
    int kbase = g * KSPLIT;

    int tm = (ltid >> 4) * 4;                      // 0..28
    int tn = (ltid & 15) * 4;                      // 0..60
    int la_m = ltid >> 2;                          // 0..31
    int la_k = (ltid & 3) * 4;                     // 0,4,8,12
    int b0_row = ltid >> 4;                        // 0..7
    int b0_col = (ltid & 15) * 4;                  // 0..60
    int b1_row = b0_row + 8;                       // 8..15

    const float* a_ptr  = lstm + (size_t)(m0 + la_m) * H_ + kbase + la_k;
    const float* b_base = bsrc + (size_t)kbase * A_;

    float acc[4][4];
#pragma unroll
    for (int i = 0; i < 4; i++)
#pragma unroll
        for (int j = 0; j < 4; j++) acc[i][j] = 0.0f;

    // prologue
    float4 av = *(const float4*)(a_ptr);
    cp16(&Bs[g][0][b0_row][b0_col], b_base + (size_t)b0_row * A_ + b0_col);
    cp16(&Bs[g][0][b1_row][b0_col], b_base + (size_t)b1_row * A_ + b0_col);
    CP_COMMIT();

    int s = 0;
    for (int k0 = 0; k0 < KSPLIT; k0 += BK, s ^= 1) {
        As[g][s][la_k + 0][la_m] = av.x;
        As[g][s][la_k + 1][la_m] = av.y;
        As[g][s][la_k + 2][la_m] = av.z;
        As[g][s][la_k + 3][la_m] = av.w;

        CP_WAIT(0);                                // this thread's B stage landed
        __syncthreads();

        if (k0 + BK < KSPLIT) {                    // prefetch next stage
            av = *(const float4*)(a_ptr + (k0 + BK));
            const float* bn_ = b_base + (size_t)(k0 + BK) * A_;
            cp16(&Bs[g][s ^ 1][b0_row][b0_col], bn_ + (size_t)b0_row * A_ + b0_col);
            cp16(&Bs[g][s ^ 1][b1_row][b0_col], bn_ + (size_t)b1_row * A_ + b0_col);
            CP_COMMIT();
        }

#pragma unroll
        for (int kk = 0; kk < BK; kk++) {
            float4 a4 = *(const float4*)&As[g][s][kk][tm];
            float4 b4 = *(const float4*)&Bs[g][s][kk][tn];
            float am[4] = {a4.x, a4.y, a4.z, a4.w};
            float bn[4] = {b4.x, b4.y, b4.z, b4.w};
#pragma unroll
            for (int i = 0; i < 4; i++)
#pragma unroll
                for (int j = 0; j < 4; j++) acc[i][j] = fmaf(am[i], bn[j], acc[i][j]);
        }
    }

    // cross-group reduction: group1 -> smem, group0 adds + epilogue
    __syncthreads();
    if (g == 1) {
#pragma unroll
        for (int i = 0; i < 4; i++)
#pragma unroll
            for (int j = 0; j < 4; j++) red[ltid * 17 + 4 * i + j] = acc[i][j];
    }
    __syncthreads();
    if (g == 0) {
#pragma unroll
        for (int i = 0; i < 4; i++)
#pragma unroll
            for (int j = 0; j < 4; j++) acc[i][j] += red[ltid * 17 + 4 * i + j];

        if (n0 < A_) {
            // wx: pack a-pairs -> g_wxh[m][a2]
#pragma unroll
            for (int i = 0; i < 4; i++) {
                int m = m0 + tm + i;
                __half2 p0 = __floats2half2_rn(acc[i][0], acc[i][1]);
                __half2 p1 = __floats2half2_rn(acc[i][2], acc[i][3]);
                __half2* dst = g_wxh + (size_t)m * (A_ / 2) + (n0 + tn) / 2;
                dst[0] = p0;
                dst[1] = p1;
            }
        } else {
            // ux: pack a-pairs, transposed -> g_uxth[b][a2][s]
            int b  = m0 >> 10;
            int s0 = (m0 & (S_ - 1)) + tm;
            int a0 = (n0 - A_) + tn;               // multiple of 4
            __half2* base = g_uxth + (size_t)b * (A_ / 2) * S_;
#pragma unroll
            for (int i = 0; i < 4; i++) {
                base[(size_t)(a0 / 2 + 0) * S_ + s0 + i] = __floats2half2_rn(acc[i][0], acc[i][1]);
                base[(size_t)(a0 / 2 + 1) * S_ + s0 + i] = __floats2half2_rn(acc[i][2], acc[i][3]);
            }
        }
    }
}

// ---------------- kernel 2: f16-native e kernel (R12, unchanged) ----------------
// dyn smem: wx_h[16][64] half2 (4KB) + uxh 2x[64][TJ] half2 (2x32KB) + v_h[64] ~68.5KB
__global__ __launch_bounds__(512) void attn_e_kernel(
    const float* __restrict__ v, float* __restrict__ attn_out)
{
    extern __shared__ float sm[];
    __half2* wx_h = (__half2*)sm;                  // MAXR*64
    __half2* uxh0 = wx_h + MAXR * (A_ / 2);        // 64 rows x TJ half2
    __half2* uxh1 = uxh0 + 64 * TJ;                // 64 rows x TJ half2
    __half2* v_h  = uxh1 + 64 * TJ;                // 64

    int tid  = threadIdx.x;
    int warp = tid >> 5;
    int lane = tid & 31;
    int blk  = blockIdx.x;                         // 148 blocks
    int b    = blk / CTAS_PER_B;
    int t_   = blk % CTAS_PER_B;
    int i0   = (S_ * t_) / CTAS_PER_B;
    int i1   = (S_ * (t_ + 1)) / CTAS_PER_B;
    int nr   = i1 - i0;                            // 13 or 14

    const __half2* uxt_b = g_uxth + (size_t)b * (A_ / 2) * S_;
    int pr = tid >> 3;                             // a2 row 0..63
    int pc = tid & 7;                              // base chunk 0..7

    // prefetch tile 0: 64 rows x 128 half2 = 32KB -> 2048 cp16 (4 per thread)
#pragma unroll
    for (int k = 0; k < 4; k++) {
        int c = 4 * (pc + 8 * k);                  // half2 offset 0..124
        cp16(uxh0 + pr * TJ + c, uxt_b + (size_t)pr * S_ + c);
    }
    CP_COMMIT();

    // stage wx rows (nr x 64 half2 = nr*256B) as uint4
    for (int x = tid; x < nr * 16; x += 512) {
        int r = x >> 4, c = x & 15;
        ((uint4*)(wx_h + r * (A_ / 2)))[c] =
            ((const uint4*)(g_wxh + (size_t)(b * S_ + i0 + r) * (A_ / 2)))[c];
    }
    if (tid < 64) v_h[tid] = __floats2half2_rn(v[2 * tid], v[2 * tid + 1]);

    bool active = (warp < nr);
    float er[4 * NT];

#pragma unroll
    for (int t = 0; t < NT; t++) {
        __half2* cur = (t & 1) ? uxh1 : uxh0;
        if (t + 1 < NT) {
            __half2* nxt = ((t + 1) & 1) ? uxh1 : uxh0;
            const __half2* src = uxt_b + (size_t)(t + 1) * TJ;
#pragma unroll
            for (int k = 0; k < 4; k++) {
                int c = 4 * (pc + 8 * k);
                cp16(nxt + pr * TJ + c, src + (size_t)pr * S_ + c);
            }
            CP_COMMIT();
            CP_WAIT(1);
        } else {
            CP_WAIT(0);
        }
        __syncthreads();

        if (active) {
            float accf0 = 0.f, accf1 = 0.f, accf2 = 0.f, accf3 = 0.f;
            const __half2* wrow = wx_h + warp * (A_ / 2);
            const __half2* ub   = cur + 4 * lane;  // this thread's 4 j-slots

#pragma unroll
            for (int g = 0; g < 8; g++) {          // spill to f32 every 16 a's
                __half2 h0 = __float2half2_rn(0.f);
                __half2 h1 = __float2half2_rn(0.f);
                __half2 h2 = __float2half2_rn(0.f);
                __half2 h3 = __float2half2_rn(0.f);
#pragma unroll
                for (int q = 0; q < 4; q++) {      // a4 = 4g+q : 4 a's = 2 tile rows
                    int a4 = 4 * g + q;
                    __half2 wh0 = wrow[2 * a4 + 0];
                    __half2 wh1 = wrow[2 * a4 + 1];
                    __half2 vh0 = v_h[2 * a4 + 0];
                    __half2 vh1 = v_h[2 * a4 + 1];
                    const __half2* r0 = ub + (size_t)(2 * a4 + 0) * TJ;
                    const __half2* r1 = ub + (size_t)(2 * a4 + 1) * TJ;
                    __half2 u00 = r0[0], u01 = r0[1], u02 = r0[2], u03 = r0[3];
                    __half2 u10 = r1[0], u11 = r1[1], u12 = r1[2], u13 = r1[3];
                    h0 = __hfma2(tanh2h(__hadd2(wh0, u00)), vh0, h0);
                    h1 = __hfma2(tanh2h(__hadd2(wh0, u01)), vh0, h1);
                    h2 = __hfma2(tanh2h(__hadd2(wh0, u02)), vh0, h2);
                    h3 = __hfma2(tanh2h(__hadd2(wh0, u03)), vh0, h3);
                    h0 = __hfma2(tanh2h(__hadd2(wh1, u10)), vh1, h0);
                    h1 = __hfma2(tanh2h(__hadd2(wh1, u11)), vh1, h1);
                    h2 = __hfma2(tanh2h(__hadd2(wh1, u12)), vh1, h2);
                    h3 = __hfma2(tanh2h(__hadd2(wh1, u13)), vh1, h3);
                }
                float2 f0 = __half22float2(h0);
                float2 f1 = __half22float2(h1);
                float2 f2 = __half22float2(h2);
                float2 f3 = __half22float2(h3);
                accf0 += f0.x + f0.y;
                accf1 += f1.x + f1.y;
                accf2 += f2.x + f2.y;
                accf3 += f3.x + f3.y;
            }
            er[4 * t + 0] = accf0;
            er[4 * t + 1] = accf1;
            er[4 * t + 2] = accf2;
            er[4 * t + 3] = accf3;
        }
        __syncthreads();
    }

    // slots region: uxh0+uxh1 = 64KB contiguous, need nr*1024*4 <= 56KB
    float* slots = (float*)uxh0;
    if (active) {
        float m = er[0];
#pragma unroll
        for (int k = 1; k < 4 * NT; k++) m = fmaxf(m, er[k]);
#pragma unroll
        for (int o = 16; o; o >>= 1) m = fmaxf(m, __shfl_xor_sync(0xffffffffu, m, o));
        float s = 0.f;
#pragma unroll
        for (int k = 0; k < 4 * NT; k++) {
            er[k] = __expf(er[k] - m);
            s += er[k];
        }
#pragma unroll
        for (int o = 16; o; o >>= 1) s += __shfl_xor_sync(0xffffffffu, s, o);
        float inv = 1.0f / s;
        float* orow = attn_out + (size_t)(b * S_ + i0 + warp) * S_;
        float* srow = slots + (size_t)warp * S_;
#pragma unroll
        for (int ti = 0; ti < NT; ti++) {
            float4 o = make_float4(er[4 * ti] * inv, er[4 * ti + 1] * inv,
                                   er[4 * ti + 2] * inv, er[4 * ti + 3] * inv);
            *(float4*)(orow + ti * TJ + 4 * lane) = o;
            *(float4*)(srow + ti * TJ + 4 * lane) = o;
        }
    }
    __syncthreads();

    for (int j = tid; j < S_; j += 512) {
        float s = 0.f;
        for (int r = 0; r < nr; r++) s += slots[(size_t)r * S_ + j];
        atomicAdd(&g_colsum[b * S_ + j], s);
    }
}

// ---------------- kernel 3: context[b,h] = sum_j colsum[b,j] * lstm[b,j,h] ----------------
__global__ __launch_bounds__(512) void context_kernel(
    const float* __restrict__ lstm, float* __restrict__ ctx)
{
    int b  = blockIdx.x >> 7;                      // 2 * 128 blocks
    int j0 = (blockIdx.x & 127) * 8;
    int h  = threadIdx.x;
    __shared__ float cs[8];
    if (threadIdx.x < 8) cs[threadIdx.x] = g_colsum[b * S_ + j0 + threadIdx.x];
    __syncthreads();
    float acc = 0.f;
    const float* lp = lstm + ((size_t)(b * S_ + j0)) * H_ + h;
#pragma unroll
    for (int j = 0; j < 8; j++) acc = fmaf(cs[j], lp[(size_t)j * H_], acc);
    atomicAdd(&ctx[b * H_ + h], acc);
}

// ---------------- launch (single stream, deterministic) ----------------
extern "C" void kernel_launch(void* const* d_in, const int* in_sizes, int n_in,
                              void* d_out, int out_size)
{
    const float* lstm = (const float*)d_in[0];
    const float* w    = (const float*)d_in[1];
    const float* u    = (const float*)d_in[2];
    const float* v    = (const float*)d_in[3];
    float* out  = (float*)d_out;
    float* ctx  = out;                // (B,H) = 1024 floats first
    float* attn = out + B_ * H_;      // (B,S,S) = 2M floats after

    gemm_wxux<<<dim3(64, 4), 256>>>(lstm, w, u, ctx);

    size_t smem = (size_t)(MAXR * (A_ / 2) + 2 * 64 * TJ + 64) * sizeof(__half2); // ~68.5 KB
    cudaFuncSetAttribute(attn_e_kernel, cudaFuncAttributeMaxDynamicSharedMemorySize, (int)smem);
    attn_e_kernel<<<B_ * CTAS_PER_B, 512, smem>>>(v, attn);

    context_kernel<<<B_ * 128, 512>>>(lstm, ctx);
}